// round 10
// baseline (speedup 1.0000x reference)
#include <cuda_runtime.h>
#include <cuda_fp16.h>
#include <cstdint>

#define N_NODES 8192
#define N_EDGES 65536
#define IN_DIM 768
#define HIDDEN 4096
#define N_CLASSES 16

// ---- scratch (device globals) ----
__device__ float g_dinv[N_NODES];
__device__ float g_logits[N_NODES * N_CLASSES];   // 512 KB
__device__ int   g_is64;
__device__ int   g_cnt[N_NODES];
__device__ int   g_off[N_NODES + 1];
__device__ int   g_cursor[N_NODES];
__device__ int   g_csr_src[N_EDGES];
// fp16 operands (single term; ~2^-12 per-element error averages to ~2.6e-5 on output)
__device__ __half g_a_hi[N_NODES * IN_DIM];       // 12.6 MB
__device__ __half g_bt_hi[HIDDEN * IN_DIM];       // 6.3 MB (W1^T)

// ============================ PTX helpers (baseline ISA only) ============================
__device__ __forceinline__ uint32_t smem_to_u32(const void* p) {
    uint32_t a;
    asm("{ .reg .u64 t; cvta.to.shared.u64 t, %1; cvt.u32.u64 %0, t; }" : "=r"(a) : "l"(p));
    return a;
}
#define CP_ASYNC16(smem, gptr) \
    asm volatile("cp.async.cg.shared.global [%0], [%1], 16;" :: "r"(smem), "l"(gptr) : "memory")
#define CP_COMMIT() asm volatile("cp.async.commit_group;" ::: "memory")
#define CP_WAIT(n)  asm volatile("cp.async.wait_group %0;" :: "n"(n) : "memory")

__device__ __forceinline__ void ldsm4(uint32_t* r, uint32_t addr) {
    asm volatile("ldmatrix.sync.aligned.m8n8.x4.shared.b16 {%0,%1,%2,%3}, [%4];"
        : "=r"(r[0]), "=r"(r[1]), "=r"(r[2]), "=r"(r[3]) : "r"(addr));
}
__device__ __forceinline__ void mma16816(float* d, const uint32_t* a, const uint32_t* b) {
    asm volatile("mma.sync.aligned.m16n8k16.row.col.f32.f16.f16.f32 "
        "{%0,%1,%2,%3}, {%4,%5,%6,%7}, {%8,%9}, {%0,%1,%2,%3};"
        : "+f"(d[0]), "+f"(d[1]), "+f"(d[2]), "+f"(d[3])
        : "r"(a[0]), "r"(a[1]), "r"(a[2]), "r"(a[3]), "r"(b[0]), "r"(b[1]));
}

__device__ __forceinline__ int edge_at(const void* ei, int idx) {
    int v;
    if (g_is64) v = (int)((const long long*)ei)[idx];
    else        v = ((const int*)ei)[idx];
    return v & (N_NODES - 1);
}

// ============================ init: zero logits/cnt + dtype detect ============================
// blocks [0,128): zero; block 128: detect
__global__ __launch_bounds__(256) void k_init(const int* __restrict__ ei32) {
    int b = blockIdx.x;
    if (b < 128) {
        int i = b * 256 + threadIdx.x;
        if (i < N_NODES * N_CLASSES / 4)
            reinterpret_cast<float4*>(g_logits)[i] = make_float4(0.f, 0.f, 0.f, 0.f);
        if (i < N_NODES / 4)
            reinterpret_cast<int4*>(g_cnt)[i] = make_int4(0, 0, 0, 0);
    } else {
        __shared__ int s_any[256];
        int any = 0;
        #pragma unroll
        for (int r = 0; r < 4; r++) {
            int i = 1 + 2 * (threadIdx.x + 256 * r);
            any |= ei32[i];
        }
        s_any[threadIdx.x] = any;
        __syncthreads();
        for (int o = 128; o > 0; o >>= 1) {
            if (threadIdx.x < o) s_any[threadIdx.x] |= s_any[threadIdx.x + o];
            __syncthreads();
        }
        if (threadIdx.x == 0) g_is64 = (s_any[0] == 0) ? 1 : 0;
    }
}

// ---- W1 [768][4096] -> transposed fp16 [4096][768] (runs on side stream) ----
__global__ __launch_bounds__(256) void k_prep_w1(const float* __restrict__ W1) {
    __shared__ float t[32][33];
    int bn = blockIdx.x & 127;
    int bk = blockIdx.x >> 7;
    int x = threadIdx.x & 31, y = threadIdx.x >> 5;
    #pragma unroll
    for (int r = 0; r < 4; r++) {
        int kl = y + r * 8;
        t[kl][x] = W1[(size_t)(bk * 32 + kl) * HIDDEN + bn * 32 + x];
    }
    __syncthreads();
    #pragma unroll
    for (int r = 0; r < 4; r++) {
        int nl = y + r * 8;
        float v = t[x][nl];
        size_t o = (size_t)(bn * 32 + nl) * IN_DIM + bk * 32 + x;
        g_bt_hi[o] = __float2half(v);
    }
}

__global__ void k_hist(const void* __restrict__ ei) {
    int e = blockIdx.x * blockDim.x + threadIdx.x;
    if (e < N_EDGES) atomicAdd(&g_cnt[edge_at(ei, N_EDGES + e)], 1);
}

// single block 1024 threads: shuffle-based scan -> offsets, cursor; dinv = rsqrt(cnt+1)
__global__ __launch_bounds__(1024) void k_scan() {
    const int t = threadIdx.x;
    const int lane = t & 31, warp = t >> 5;
    const int base = t * 8;
    int v[8];
    int s = 0;
    #pragma unroll
    for (int i = 0; i < 8; i++) { v[i] = g_cnt[base + i]; s += v[i]; }
    int inc = s;
    #pragma unroll
    for (int o = 1; o < 32; o <<= 1) {
        int y = __shfl_up_sync(0xffffffffu, inc, o);
        if (lane >= o) inc += y;
    }
    __shared__ int wsum[32];
    if (lane == 31) wsum[warp] = inc;
    __syncthreads();
    if (warp == 0) {
        int ws = wsum[lane];
        int wi = ws;
        #pragma unroll
        for (int o = 1; o < 32; o <<= 1) {
            int y = __shfl_up_sync(0xffffffffu, wi, o);
            if (lane >= o) wi += y;
        }
        wsum[lane] = wi - ws;
    }
    __syncthreads();
    int run = wsum[warp] + inc - s;
    #pragma unroll
    for (int i = 0; i < 8; i++) {
        g_off[base + i] = run;
        g_cursor[base + i] = run;
        g_dinv[base + i] = rsqrtf((float)(v[i] + 1));
        run += v[i];
    }
    if (t == 1023) g_off[N_NODES] = run;
}

__global__ void k_fill(const void* __restrict__ ei) {
    int e = blockIdx.x * blockDim.x + threadIdx.x;
    if (e >= N_EDGES) return;
    int s = edge_at(ei, e);
    int d = edge_at(ei, N_EDGES + e);
    int pos = atomicAdd(&g_cursor[d], 1);
    g_csr_src[pos] = s;
}

// ---- gather aggregation (warp per node) + fp16 write ----
__global__ __launch_bounds__(256) void k_gather(const float* __restrict__ x) {
    int v = blockIdx.x * 8 + (threadIdx.x >> 5);
    int lane = threadIdx.x & 31;
    float dv = g_dinv[v];
    const float4* xv = reinterpret_cast<const float4*>(x + (size_t)v * IN_DIM);
    float4 acc[6];
    float sw = dv * dv;
    #pragma unroll
    for (int t = 0; t < 6; t++) {
        float4 a = xv[lane + 32 * t];
        acc[t].x = a.x * sw; acc[t].y = a.y * sw;
        acc[t].z = a.z * sw; acc[t].w = a.w * sw;
    }
    int e0 = g_off[v], e1 = g_off[v + 1];
    for (int p = e0; p < e1; p++) {
        int s = g_csr_src[p];
        float w = g_dinv[s] * dv;
        const float4* xs = reinterpret_cast<const float4*>(x + (size_t)s * IN_DIM);
        #pragma unroll
        for (int t = 0; t < 6; t++) {
            float4 a = xs[lane + 32 * t];
            acc[t].x += a.x * w; acc[t].y += a.y * w;
            acc[t].z += a.z * w; acc[t].w += a.w * w;
        }
    }
    #pragma unroll
    for (int t = 0; t < 6; t++) {
        int eb = v * IN_DIM + lane * 4 + 128 * t;
        __half2 h01 = __halves2half2(__float2half(acc[t].x), __float2half(acc[t].y));
        __half2 h23 = __halves2half2(__float2half(acc[t].z), __float2half(acc[t].w));
        *reinterpret_cast<uint2*>(g_a_hi + eb) =
            make_uint2(*(uint32_t*)&h01, *(uint32_t*)&h23);
    }
}

// ============================ HMMA GEMM (single-term fp16, 4-stage) ============================
// Per 32-wide k-chunk, stage {Ah, Bh} (16KB); 4-stage cp.async pipeline.
// Block tile 128x128, 8 warps (2M x 4N), warp tile 64x32.
#define KCHUNK 24
#define STAGE_B 16384
#define H_STRIDE 130
#define W2S_OFF 66560               // h buffer 128*130*4 = 66560 >= 4*16384 stages
#define B1S_OFF (W2S_OFF + 8192)
#define SMEM_TOTAL (B1S_OFF + 512)

__global__ __launch_bounds__(256, 2) void k_gemm_mma(const float* __restrict__ b1,
                                                     const float* __restrict__ W2) {
    extern __shared__ __align__(128) char smem[];
    const uint32_t sb = smem_to_u32(smem);
    const int tid = threadIdx.x, lane = tid & 31, wid = tid >> 5;
    const int wm = wid & 1, wn = wid >> 1;
    const int bx = blockIdx.x, by = blockIdx.y;

    // stage W2 slice (128x16 f32) + b1 slice (128 f32)
    {
        const float4* s = reinterpret_cast<const float4*>(W2 + (size_t)bx * 128 * N_CLASSES);
        float4* d = reinterpret_cast<float4*>(smem + W2S_OFF);
        #pragma unroll
        for (int i = tid; i < 512; i += 256) d[i] = s[i];
        if (tid < 128) reinterpret_cast<float*>(smem + B1S_OFF)[tid] = b1[bx * 128 + tid];
    }

    float c[4][4][4];
    #pragma unroll
    for (int mi = 0; mi < 4; mi++)
        #pragma unroll
        for (int ni = 0; ni < 4; ni++)
            #pragma unroll
            for (int q = 0; q < 4; q++) c[mi][ni][q] = 0.0f;

    const int row_half = tid >> 2;       // 0..63
    const int chk = tid & 3;
    const int arow_g = by * 128;
    const int brow_g = bx * 128;

    auto load_stage = [&](int ch) {
        int kk = ch * 32;
        uint32_t sbase = sb + (ch & 3) * STAGE_B;
        #pragma unroll
        for (int half = 0; half < 2; half++) {
            int row = row_half + half * 64;
            uint32_t soff = row * 64 + ((chk ^ (row & 3)) << 4);
            size_t goff = (size_t)row * IN_DIM + kk + chk * 8;
            CP_ASYNC16(sbase +    0 + soff, g_a_hi  + (size_t)arow_g * IN_DIM + goff);
            CP_ASYNC16(sbase + 8192 + soff, g_bt_hi + (size_t)brow_g * IN_DIM + goff);
        }
        CP_COMMIT();
    };

    load_stage(0);
    load_stage(1);
    load_stage(2);

    #pragma unroll 4
    for (int ch = 0; ch < KCHUNK; ch++) {
        if (ch + 3 < KCHUNK) { CP_WAIT(2); } else { CP_WAIT(0); }
        __syncthreads();
        if (ch + 3 < KCHUNK) load_stage(ch + 3);

        uint32_t aHB = sb + (ch & 3) * STAGE_B;
        uint32_t bHB = aHB + 8192;

        #pragma unroll
        for (int kk = 0; kk < 2; kk++) {
            uint32_t a[4][4], bh[4][2];
            int arow = wm * 64 + (lane & 15);
            int akc = kk * 2 + (lane >> 4);
            #pragma unroll
            for (int mi = 0; mi < 4; mi++) {
                int row = arow + mi * 16;
                ldsm4(a[mi], aHB + row * 64 + ((akc ^ (row & 3)) << 4));
            }
            int bnl = (lane & 7) + ((lane >> 4) << 3);
            int bkc = kk * 2 + ((lane >> 3) & 1);
            #pragma unroll
            for (int nn = 0; nn < 2; nn++) {
                int n = wn * 32 + nn * 16 + bnl;
                uint32_t t[4];
                ldsm4(t, bHB + n * 64 + ((bkc ^ (n & 3)) << 4));
                bh[nn * 2][0] = t[0]; bh[nn * 2][1] = t[1];
                bh[nn * 2 + 1][0] = t[2]; bh[nn * 2 + 1][1] = t[3];
            }
            #pragma unroll
            for (int mi = 0; mi < 4; mi++)
                #pragma unroll
                for (int ni = 0; ni < 4; ni++)
                    mma16816(c[mi][ni], a[mi], bh[ni]);
        }
    }

    // epilogue: stage h to smem, then h @ W2 slice -> atomic logits
    __syncthreads();
    float* h = reinterpret_cast<float*>(smem);
    const float* b1s = reinterpret_cast<const float*>(smem + B1S_OFF);
    #pragma unroll
    for (int mi = 0; mi < 4; mi++) {
        int r0 = wm * 64 + mi * 16 + (lane >> 2);
        #pragma unroll
        for (int ni = 0; ni < 4; ni++) {
            int n = wn * 32 + ni * 8 + (lane & 3) * 2;
            *reinterpret_cast<float2*>(&h[r0 * H_STRIDE + n]) =
                make_float2(c[mi][ni][0], c[mi][ni][1]);
            *reinterpret_cast<float2*>(&h[(r0 + 8) * H_STRIDE + n]) =
                make_float2(c[mi][ni][2], c[mi][ni][3]);
        }
    }
    __syncthreads();
    {
        int r = tid >> 1;
        int cg = (tid & 1) * 8;
        const float* w2s = reinterpret_cast<const float*>(smem + W2S_OFF);
        float acc[8];
        #pragma unroll
        for (int q = 0; q < 8; q++) acc[q] = 0.0f;
        #pragma unroll 4
        for (int n = 0; n < 128; n++) {
            float hv = fmaxf(h[r * H_STRIDE + n] + b1s[n], 0.0f);
            const float4* w = reinterpret_cast<const float4*>(w2s + n * N_CLASSES + cg);
            float4 w0 = w[0], w1 = w[1];
            acc[0] += hv * w0.x; acc[1] += hv * w0.y;
            acc[2] += hv * w0.z; acc[3] += hv * w0.w;
            acc[4] += hv * w1.x; acc[5] += hv * w1.y;
            acc[6] += hv * w1.z; acc[7] += hv * w1.w;
        }
        float* lg = &g_logits[(by * 128 + r) * N_CLASSES + cg];
        #pragma unroll
        for (int q = 0; q < 8; q++) atomicAdd(&lg[q], acc[q]);
    }
}

// ---- log_softmax over 16 classes ----
__global__ void k_lsm(const float* __restrict__ b2, float* __restrict__ out) {
    int t = blockIdx.x * blockDim.x + threadIdx.x;
    if (t >= N_NODES * N_CLASSES) return;
    int c = t & 15;
    float v = g_logits[t] + b2[c];
    float m = v;
    #pragma unroll
    for (int k = 8; k > 0; k >>= 1)
        m = fmaxf(m, __shfl_xor_sync(0xffffffffu, m, k, 16));
    float s = __expf(v - m);
    #pragma unroll
    for (int k = 8; k > 0; k >>= 1)
        s += __shfl_xor_sync(0xffffffffu, s, k, 16);
    out[t] = v - m - __logf(s);
}

// ---- eager module load + persistent stream/events for capture-time fork ----
namespace {
cudaStream_t g_s2 = nullptr;
cudaEvent_t g_ev_fork = nullptr, g_ev_join = nullptr;
struct EagerLoad {
    EagerLoad() {
        void* p = nullptr;
        cudaGetSymbolAddress(&p, g_logits);
        cudaGetSymbolAddress(&p, g_dinv);
        cudaGetSymbolAddress(&p, g_is64);
        cudaGetSymbolAddress(&p, g_cnt);
        cudaGetSymbolAddress(&p, g_off);
        cudaGetSymbolAddress(&p, g_cursor);
        cudaGetSymbolAddress(&p, g_csr_src);
        cudaGetSymbolAddress(&p, g_a_hi);
        cudaGetSymbolAddress(&p, g_bt_hi);
        cudaFuncAttributes a;
        cudaFuncGetAttributes(&a, k_init);
        cudaFuncGetAttributes(&a, k_prep_w1);
        cudaFuncGetAttributes(&a, k_hist);
        cudaFuncGetAttributes(&a, k_scan);
        cudaFuncGetAttributes(&a, k_fill);
        cudaFuncGetAttributes(&a, k_gather);
        cudaFuncGetAttributes(&a, k_gemm_mma);
        cudaFuncGetAttributes(&a, k_lsm);
        cudaFuncSetAttribute(k_gemm_mma, cudaFuncAttributeMaxDynamicSharedMemorySize, SMEM_TOTAL);
        cudaStreamCreateWithFlags(&g_s2, cudaStreamNonBlocking);
        cudaEventCreateWithFlags(&g_ev_fork, cudaEventDisableTiming);
        cudaEventCreateWithFlags(&g_ev_join, cudaEventDisableTiming);
    }
};
EagerLoad g_eager_load;
}

extern "C" void kernel_launch(void* const* d_in, const int* in_sizes, int n_in,
                              void* d_out, int out_size) {
    const float* x  = (const float*)d_in[0];
    const void*  ei = d_in[1];                 // [2, E], int32 OR int64 (detected)
    const float* W1 = (const float*)d_in[2];
    const float* b1 = (const float*)d_in[3];
    const float* W2 = (const float*)d_in[4];
    const float* b2 = (const float*)d_in[5];
    float* out = (float*)d_out;

    // fork: W1 transpose runs on side stream, overlapped with the edge chain
    bool forked = false;
    if (g_s2 && g_ev_fork && g_ev_join &&
        cudaEventRecord(g_ev_fork, 0) == cudaSuccess &&
        cudaStreamWaitEvent(g_s2, g_ev_fork, 0) == cudaSuccess) {
        k_prep_w1<<<3072, 256, 0, g_s2>>>(W1);
        cudaEventRecord(g_ev_join, g_s2);
        forked = true;
    } else {
        k_prep_w1<<<3072, 256>>>(W1);
    }

    k_init<<<129, 256>>>((const int*)ei);
    k_hist<<<(N_EDGES + 255) / 256, 256>>>(ei);
    k_scan<<<1, 1024>>>();
    k_fill<<<(N_EDGES + 255) / 256, 256>>>(ei);
    k_gather<<<N_NODES / 8, 256>>>(x);

    if (forked) cudaStreamWaitEvent(0, g_ev_join, 0);

    k_gemm_mma<<<dim3(HIDDEN / 128, N_NODES / 128), 256, SMEM_TOTAL>>>(b1, W2);
    k_lsm<<<(N_NODES * N_CLASSES + 255) / 256, 256>>>(b2, out);
}

// round 11
// speedup vs baseline: 1.0725x; 1.0725x over previous
#include <cuda_runtime.h>
#include <cuda_fp16.h>
#include <cstdint>

#define N_NODES 8192
#define N_EDGES 65536
#define IN_DIM 768
#define HIDDEN 4096
#define N_CLASSES 16

// ---- scratch (device globals) ----
__device__ float g_dinv[N_NODES];
__device__ float g_logits[N_NODES * N_CLASSES];   // 512 KB
__device__ int   g_is64;
__device__ int   g_cnt[N_NODES];
__device__ int   g_off[N_NODES + 1];
__device__ int   g_cursor[N_NODES];
__device__ int   g_csr_src[N_EDGES];
__device__ int   g_bsum[8];
// fp16 operands (single term; ~2^-12 per-element error averages to ~2.6e-5 on output)
__device__ __half g_a_hi[N_NODES * IN_DIM];       // 12.6 MB
__device__ __half g_bt_hi[HIDDEN * IN_DIM];       // 6.3 MB (W1^T)

// ============================ PTX helpers (baseline ISA only) ============================
__device__ __forceinline__ uint32_t smem_to_u32(const void* p) {
    uint32_t a;
    asm("{ .reg .u64 t; cvta.to.shared.u64 t, %1; cvt.u32.u64 %0, t; }" : "=r"(a) : "l"(p));
    return a;
}
#define CP_ASYNC16(smem, gptr) \
    asm volatile("cp.async.cg.shared.global [%0], [%1], 16;" :: "r"(smem), "l"(gptr) : "memory")
#define CP_COMMIT() asm volatile("cp.async.commit_group;" ::: "memory")
#define CP_WAIT(n)  asm volatile("cp.async.wait_group %0;" :: "n"(n) : "memory")

__device__ __forceinline__ void ldsm4(uint32_t* r, uint32_t addr) {
    asm volatile("ldmatrix.sync.aligned.m8n8.x4.shared.b16 {%0,%1,%2,%3}, [%4];"
        : "=r"(r[0]), "=r"(r[1]), "=r"(r[2]), "=r"(r[3]) : "r"(addr));
}
__device__ __forceinline__ void mma16816(float* d, const uint32_t* a, const uint32_t* b) {
    asm volatile("mma.sync.aligned.m16n8k16.row.col.f32.f16.f16.f32 "
        "{%0,%1,%2,%3}, {%4,%5,%6,%7}, {%8,%9}, {%0,%1,%2,%3};"
        : "+f"(d[0]), "+f"(d[1]), "+f"(d[2]), "+f"(d[3])
        : "r"(a[0]), "r"(a[1]), "r"(a[2]), "r"(a[3]), "r"(b[0]), "r"(b[1]));
}

__device__ __forceinline__ int edge_at(const void* ei, int idx) {
    int v;
    if (g_is64) v = (int)((const long long*)ei)[idx];
    else        v = ((const int*)ei)[idx];
    return v & (N_NODES - 1);
}

// ============================ merged prep: W1 transpose + zero + detect ============================
// blocks [0,3072): prep_bt; [3072,3200): zero logits/cnt; block 3200: dtype detect
__global__ __launch_bounds__(256) void k_prep_all(const float* __restrict__ W1,
                                                  const int* __restrict__ ei32) {
    int b = blockIdx.x;
    if (b < 3072) {
        __shared__ float t[32][33];
        int bn = b & 127;
        int bk = b >> 7;
        int x = threadIdx.x & 31, y = threadIdx.x >> 5;
        #pragma unroll
        for (int r = 0; r < 4; r++) {
            int kl = y + r * 8;
            t[kl][x] = W1[(size_t)(bk * 32 + kl) * HIDDEN + bn * 32 + x];
        }
        __syncthreads();
        #pragma unroll
        for (int r = 0; r < 4; r++) {
            int nl = y + r * 8;
            float v = t[x][nl];
            size_t o = (size_t)(bn * 32 + nl) * IN_DIM + bk * 32 + x;
            g_bt_hi[o] = __float2half(v);
        }
    } else if (b < 3200) {
        int i = (b - 3072) * 256 + threadIdx.x;
        if (i < N_NODES * N_CLASSES / 4)
            reinterpret_cast<float4*>(g_logits)[i] = make_float4(0.f, 0.f, 0.f, 0.f);
        if (i < N_NODES / 4)
            reinterpret_cast<int4*>(g_cnt)[i] = make_int4(0, 0, 0, 0);
    } else {
        __shared__ int s_any[256];
        int any = 0;
        #pragma unroll
        for (int r = 0; r < 4; r++) {
            int i = 1 + 2 * (threadIdx.x + 256 * r);
            any |= ei32[i];
        }
        s_any[threadIdx.x] = any;
        __syncthreads();
        for (int o = 128; o > 0; o >>= 1) {
            if (threadIdx.x < o) s_any[threadIdx.x] |= s_any[threadIdx.x + o];
            __syncthreads();
        }
        if (threadIdx.x == 0) g_is64 = (s_any[0] == 0) ? 1 : 0;
    }
}

__global__ void k_hist(const void* __restrict__ ei) {
    int e = blockIdx.x * blockDim.x + threadIdx.x;
    if (e < N_EDGES) atomicAdd(&g_cnt[edge_at(ei, N_EDGES + e)], 1);
}

// ---- two-phase scan: 8 blocks x 1024 threads each ----
__global__ __launch_bounds__(1024) void k_scan1() {
    const int b = blockIdx.x, t = threadIdx.x;
    const int i = b * 1024 + t;
    const int lane = t & 31, warp = t >> 5;
    int v = g_cnt[i];
    int inc = v;
    #pragma unroll
    for (int o = 1; o < 32; o <<= 1) {
        int y = __shfl_up_sync(0xffffffffu, inc, o);
        if (lane >= o) inc += y;
    }
    __shared__ int wsum[32];
    __shared__ int btot;
    if (lane == 31) wsum[warp] = inc;
    __syncthreads();
    if (warp == 0) {
        int ws = wsum[lane];
        int wi = ws;
        #pragma unroll
        for (int o = 1; o < 32; o <<= 1) {
            int y = __shfl_up_sync(0xffffffffu, wi, o);
            if (lane >= o) wi += y;
        }
        wsum[lane] = wi - ws;
        if (lane == 31) btot = wi;
    }
    __syncthreads();
    g_off[i] = wsum[warp] + inc - v;    // block-local exclusive prefix
    g_dinv[i] = rsqrtf((float)(v + 1));
    if (t == 0) g_bsum[b] = btot;
}
__global__ __launch_bounds__(1024) void k_scan2() {
    const int b = blockIdx.x, t = threadIdx.x;
    const int i = b * 1024 + t;
    int base = 0, tot = 0;
    #pragma unroll
    for (int j = 0; j < 8; j++) {
        int s = g_bsum[j];
        if (j < b) base += s;
        tot += s;
    }
    int o = g_off[i] + base;
    g_off[i] = o;
    g_cursor[i] = o;
    if (b == 7 && t == 1023) g_off[N_NODES] = tot;
}

__global__ void k_fill(const void* __restrict__ ei) {
    int e = blockIdx.x * blockDim.x + threadIdx.x;
    if (e >= N_EDGES) return;
    int s = edge_at(ei, e);
    int d = edge_at(ei, N_EDGES + e);
    int pos = atomicAdd(&g_cursor[d], 1);
    g_csr_src[pos] = s;
}

// ---- gather aggregation (warp per node) + fp16 write ----
__global__ __launch_bounds__(256) void k_gather(const float* __restrict__ x) {
    int v = blockIdx.x * 8 + (threadIdx.x >> 5);
    int lane = threadIdx.x & 31;
    float dv = g_dinv[v];
    const float4* xv = reinterpret_cast<const float4*>(x + (size_t)v * IN_DIM);
    float4 acc[6];
    float sw = dv * dv;
    #pragma unroll
    for (int t = 0; t < 6; t++) {
        float4 a = xv[lane + 32 * t];
        acc[t].x = a.x * sw; acc[t].y = a.y * sw;
        acc[t].z = a.z * sw; acc[t].w = a.w * sw;
    }
    int e0 = g_off[v], e1 = g_off[v + 1];
    for (int p = e0; p < e1; p++) {
        int s = g_csr_src[p];
        float w = g_dinv[s] * dv;
        const float4* xs = reinterpret_cast<const float4*>(x + (size_t)s * IN_DIM);
        #pragma unroll
        for (int t = 0; t < 6; t++) {
            float4 a = xs[lane + 32 * t];
            acc[t].x += a.x * w; acc[t].y += a.y * w;
            acc[t].z += a.z * w; acc[t].w += a.w * w;
        }
    }
    #pragma unroll
    for (int t = 0; t < 6; t++) {
        int eb = v * IN_DIM + lane * 4 + 128 * t;
        __half2 h01 = __halves2half2(__float2half(acc[t].x), __float2half(acc[t].y));
        __half2 h23 = __halves2half2(__float2half(acc[t].z), __float2half(acc[t].w));
        *reinterpret_cast<uint2*>(g_a_hi + eb) =
            make_uint2(*(uint32_t*)&h01, *(uint32_t*)&h23);
    }
}

// ============================ HMMA GEMM (single-term fp16) ============================
// Per 32-wide k-chunk, stage {Ah, Bh} (16KB); 3-stage cp.async pipeline.
// Block tile 128x128, 8 warps (2M x 4N), warp tile 64x32.
#define KCHUNK 24
#define STAGE_B 16384
#define H_STRIDE 130
#define W2S_OFF 66560
#define B1S_OFF (W2S_OFF + 8192)
#define SMEM_TOTAL (B1S_OFF + 512)

__global__ __launch_bounds__(256, 2) void k_gemm_mma(const float* __restrict__ b1,
                                                     const float* __restrict__ W2) {
    extern __shared__ __align__(128) char smem[];
    const uint32_t sb = smem_to_u32(smem);
    const int tid = threadIdx.x, lane = tid & 31, wid = tid >> 5;
    const int wm = wid & 1, wn = wid >> 1;
    const int bx = blockIdx.x, by = blockIdx.y;

    // stage W2 slice (128x16 f32) + b1 slice (128 f32)
    {
        const float4* s = reinterpret_cast<const float4*>(W2 + (size_t)bx * 128 * N_CLASSES);
        float4* d = reinterpret_cast<float4*>(smem + W2S_OFF);
        #pragma unroll
        for (int i = tid; i < 512; i += 256) d[i] = s[i];
        if (tid < 128) reinterpret_cast<float*>(smem + B1S_OFF)[tid] = b1[bx * 128 + tid];
    }

    float c[4][4][4];
    #pragma unroll
    for (int mi = 0; mi < 4; mi++)
        #pragma unroll
        for (int ni = 0; ni < 4; ni++)
            #pragma unroll
            for (int q = 0; q < 4; q++) c[mi][ni][q] = 0.0f;

    const int row_half = tid >> 2;       // 0..63
    const int chk = tid & 3;
    const int arow_g = by * 128;
    const int brow_g = bx * 128;

    auto load_stage = [&](int ch, int buf) {
        int kk = ch * 32;
        uint32_t sbase = sb + buf * STAGE_B;
        #pragma unroll
        for (int half = 0; half < 2; half++) {
            int row = row_half + half * 64;
            uint32_t soff = row * 64 + ((chk ^ (row & 3)) << 4);
            size_t goff = (size_t)row * IN_DIM + kk + chk * 8;
            CP_ASYNC16(sbase +    0 + soff, g_a_hi  + (size_t)arow_g * IN_DIM + goff);
            CP_ASYNC16(sbase + 8192 + soff, g_bt_hi + (size_t)brow_g * IN_DIM + goff);
        }
        CP_COMMIT();
    };

    load_stage(0, 0);
    load_stage(1, 1);

    #pragma unroll 3
    for (int ch = 0; ch < KCHUNK; ch++) {
        if (ch + 2 < KCHUNK) { CP_WAIT(1); } else { CP_WAIT(0); }
        __syncthreads();
        if (ch + 2 < KCHUNK) load_stage(ch + 2, (ch + 2) % 3);

        uint32_t aHB = sb + (ch % 3) * STAGE_B;
        uint32_t bHB = aHB + 8192;

        #pragma unroll
        for (int kk = 0; kk < 2; kk++) {
            uint32_t a[4][4], bh[4][2];
            int arow = wm * 64 + (lane & 15);
            int akc = kk * 2 + (lane >> 4);
            #pragma unroll
            for (int mi = 0; mi < 4; mi++) {
                int row = arow + mi * 16;
                ldsm4(a[mi], aHB + row * 64 + ((akc ^ (row & 3)) << 4));
            }
            int bnl = (lane & 7) + ((lane >> 4) << 3);
            int bkc = kk * 2 + ((lane >> 3) & 1);
            #pragma unroll
            for (int nn = 0; nn < 2; nn++) {
                int n = wn * 32 + nn * 16 + bnl;
                uint32_t t[4];
                ldsm4(t, bHB + n * 64 + ((bkc ^ (n & 3)) << 4));
                bh[nn * 2][0] = t[0]; bh[nn * 2][1] = t[1];
                bh[nn * 2 + 1][0] = t[2]; bh[nn * 2 + 1][1] = t[3];
            }
            #pragma unroll
            for (int mi = 0; mi < 4; mi++)
                #pragma unroll
                for (int ni = 0; ni < 4; ni++)
                    mma16816(c[mi][ni], a[mi], bh[ni]);
        }
    }

    // epilogue: stage h to smem, then h @ W2 slice -> atomic logits
    __syncthreads();
    float* h = reinterpret_cast<float*>(smem);
    const float* b1s = reinterpret_cast<const float*>(smem + B1S_OFF);
    #pragma unroll
    for (int mi = 0; mi < 4; mi++) {
        int r0 = wm * 64 + mi * 16 + (lane >> 2);
        #pragma unroll
        for (int ni = 0; ni < 4; ni++) {
            int n = wn * 32 + ni * 8 + (lane & 3) * 2;
            *reinterpret_cast<float2*>(&h[r0 * H_STRIDE + n]) =
                make_float2(c[mi][ni][0], c[mi][ni][1]);
            *reinterpret_cast<float2*>(&h[(r0 + 8) * H_STRIDE + n]) =
                make_float2(c[mi][ni][2], c[mi][ni][3]);
        }
    }
    __syncthreads();
    {
        int r = tid >> 1;
        int cg = (tid & 1) * 8;
        const float* w2s = reinterpret_cast<const float*>(smem + W2S_OFF);
        float acc[8];
        #pragma unroll
        for (int q = 0; q < 8; q++) acc[q] = 0.0f;
        #pragma unroll 4
        for (int n = 0; n < 128; n++) {
            float hv = fmaxf(h[r * H_STRIDE + n] + b1s[n], 0.0f);
            const float4* w = reinterpret_cast<const float4*>(w2s + n * N_CLASSES + cg);
            float4 w0 = w[0], w1 = w[1];
            acc[0] += hv * w0.x; acc[1] += hv * w0.y;
            acc[2] += hv * w0.z; acc[3] += hv * w0.w;
            acc[4] += hv * w1.x; acc[5] += hv * w1.y;
            acc[6] += hv * w1.z; acc[7] += hv * w1.w;
        }
        float* lg = &g_logits[(by * 128 + r) * N_CLASSES + cg];
        #pragma unroll
        for (int q = 0; q < 8; q++) atomicAdd(&lg[q], acc[q]);
    }
}

// ---- log_softmax over 16 classes ----
__global__ void k_lsm(const float* __restrict__ b2, float* __restrict__ out) {
    int t = blockIdx.x * blockDim.x + threadIdx.x;
    if (t >= N_NODES * N_CLASSES) return;
    int c = t & 15;
    float v = g_logits[t] + b2[c];
    float m = v;
    #pragma unroll
    for (int k = 8; k > 0; k >>= 1)
        m = fmaxf(m, __shfl_xor_sync(0xffffffffu, m, k, 16));
    float s = __expf(v - m);
    #pragma unroll
    for (int k = 8; k > 0; k >>= 1)
        s += __shfl_xor_sync(0xffffffffu, s, k, 16);
    out[t] = v - m - __logf(s);
}

// ---- eager module load ----
namespace {
struct EagerLoad {
    EagerLoad() {
        void* p = nullptr;
        cudaGetSymbolAddress(&p, g_logits);
        cudaGetSymbolAddress(&p, g_dinv);
        cudaGetSymbolAddress(&p, g_is64);
        cudaGetSymbolAddress(&p, g_cnt);
        cudaGetSymbolAddress(&p, g_off);
        cudaGetSymbolAddress(&p, g_cursor);
        cudaGetSymbolAddress(&p, g_csr_src);
        cudaGetSymbolAddress(&p, g_bsum);
        cudaGetSymbolAddress(&p, g_a_hi);
        cudaGetSymbolAddress(&p, g_bt_hi);
        cudaFuncAttributes a;
        cudaFuncGetAttributes(&a, k_prep_all);
        cudaFuncGetAttributes(&a, k_hist);
        cudaFuncGetAttributes(&a, k_scan1);
        cudaFuncGetAttributes(&a, k_scan2);
        cudaFuncGetAttributes(&a, k_fill);
        cudaFuncGetAttributes(&a, k_gather);
        cudaFuncGetAttributes(&a, k_gemm_mma);
        cudaFuncGetAttributes(&a, k_lsm);
        cudaFuncSetAttribute(k_gemm_mma, cudaFuncAttributeMaxDynamicSharedMemorySize, SMEM_TOTAL);
    }
};
EagerLoad g_eager_load;
}

extern "C" void kernel_launch(void* const* d_in, const int* in_sizes, int n_in,
                              void* d_out, int out_size) {
    const float* x  = (const float*)d_in[0];
    const void*  ei = d_in[1];                 // [2, E], int32 OR int64 (detected)
    const float* W1 = (const float*)d_in[2];
    const float* b1 = (const float*)d_in[3];
    const float* W2 = (const float*)d_in[4];
    const float* b2 = (const float*)d_in[5];
    float* out = (float*)d_out;

    k_prep_all<<<3201, 256>>>(W1, (const int*)ei);
    k_hist<<<(N_EDGES + 255) / 256, 256>>>(ei);
    k_scan1<<<8, 1024>>>();
    k_scan2<<<8, 1024>>>();
    k_fill<<<(N_EDGES + 255) / 256, 256>>>(ei);
    k_gather<<<N_NODES / 8, 256>>>(x);

    k_gemm_mma<<<dim3(HIDDEN / 128, N_NODES / 128), 256, SMEM_TOTAL>>>(b1, W2);
    k_lsm<<<(N_NODES * N_CLASSES + 255) / 256, 256>>>(b2, out);
}

// round 12
// speedup vs baseline: 1.3665x; 1.2741x over previous
#include <cuda_runtime.h>
#include <cuda_fp16.h>
#include <cstdint>

#define N_NODES 8192
#define N_EDGES 65536
#define IN_DIM 768
#define HIDDEN 4096
#define N_CLASSES 16

// ---- scratch (device globals) ----
__device__ float g_dinv[N_NODES];
__device__ float g_logits[N_NODES * N_CLASSES];   // 512 KB
__device__ int   g_is64;
__device__ int   g_cnt[N_NODES];
__device__ int   g_off[N_NODES + 1];
__device__ int   g_cursor[N_NODES];
__device__ int   g_csr_src[N_EDGES];
__device__ int   g_bsum[8];
// fp16 operands (single term; ~2^-12 per-element error averages to ~2.6e-5 on output)
__device__ __half g_a_hi[N_NODES * IN_DIM];       // 12.6 MB
__device__ __half g_bt_hi[HIDDEN * IN_DIM];       // 6.3 MB (W1^T)

// ============================ PTX helpers (baseline ISA only) ============================
__device__ __forceinline__ uint32_t smem_to_u32(const void* p) {
    uint32_t a;
    asm("{ .reg .u64 t; cvta.to.shared.u64 t, %1; cvt.u32.u64 %0, t; }" : "=r"(a) : "l"(p));
    return a;
}
#define CP_ASYNC16(smem, gptr) \
    asm volatile("cp.async.cg.shared.global [%0], [%1], 16;" :: "r"(smem), "l"(gptr) : "memory")
#define CP_COMMIT() asm volatile("cp.async.commit_group;" ::: "memory")
#define CP_WAIT(n)  asm volatile("cp.async.wait_group %0;" :: "n"(n) : "memory")

__device__ __forceinline__ void ldsm4(uint32_t* r, uint32_t addr) {
    asm volatile("ldmatrix.sync.aligned.m8n8.x4.shared.b16 {%0,%1,%2,%3}, [%4];"
        : "=r"(r[0]), "=r"(r[1]), "=r"(r[2]), "=r"(r[3]) : "r"(addr));
}
__device__ __forceinline__ void mma16816(float* d, const uint32_t* a, const uint32_t* b) {
    asm volatile("mma.sync.aligned.m16n8k16.row.col.f32.f16.f16.f32 "
        "{%0,%1,%2,%3}, {%4,%5,%6,%7}, {%8,%9}, {%0,%1,%2,%3};"
        : "+f"(d[0]), "+f"(d[1]), "+f"(d[2]), "+f"(d[3])
        : "r"(a[0]), "r"(a[1]), "r"(a[2]), "r"(a[3]), "r"(b[0]), "r"(b[1]));
}

__device__ __forceinline__ int edge_at(const void* ei, int idx) {
    int v;
    if (g_is64) v = (int)((const long long*)ei)[idx];
    else        v = ((const int*)ei)[idx];
    return v & (N_NODES - 1);
}

// ============================ merged prep: W1 transpose + zero + detect ============================
// blocks [0,3072): prep_bt; [3072,3200): zero logits/cnt; block 3200: dtype detect
__global__ __launch_bounds__(256) void k_prep_all(const float* __restrict__ W1,
                                                  const int* __restrict__ ei32) {
    int b = blockIdx.x;
    if (b < 3072) {
        __shared__ float t[32][33];
        int bn = b & 127;
        int bk = b >> 7;
        int x = threadIdx.x & 31, y = threadIdx.x >> 5;
        #pragma unroll
        for (int r = 0; r < 4; r++) {
            int kl = y + r * 8;
            t[kl][x] = W1[(size_t)(bk * 32 + kl) * HIDDEN + bn * 32 + x];
        }
        __syncthreads();
        #pragma unroll
        for (int r = 0; r < 4; r++) {
            int nl = y + r * 8;
            float v = t[x][nl];
            size_t o = (size_t)(bn * 32 + nl) * IN_DIM + bk * 32 + x;
            g_bt_hi[o] = __float2half(v);
        }
    } else if (b < 3200) {
        int i = (b - 3072) * 256 + threadIdx.x;
        if (i < N_NODES * N_CLASSES / 4)
            reinterpret_cast<float4*>(g_logits)[i] = make_float4(0.f, 0.f, 0.f, 0.f);
        if (i < N_NODES / 4)
            reinterpret_cast<int4*>(g_cnt)[i] = make_int4(0, 0, 0, 0);
    } else {
        __shared__ int s_any[256];
        int any = 0;
        #pragma unroll
        for (int r = 0; r < 4; r++) {
            int i = 1 + 2 * (threadIdx.x + 256 * r);
            any |= ei32[i];
        }
        s_any[threadIdx.x] = any;
        __syncthreads();
        for (int o = 128; o > 0; o >>= 1) {
            if (threadIdx.x < o) s_any[threadIdx.x] |= s_any[threadIdx.x + o];
            __syncthreads();
        }
        if (threadIdx.x == 0) g_is64 = (s_any[0] == 0) ? 1 : 0;
    }
}

__global__ void k_hist(const void* __restrict__ ei) {
    int e = blockIdx.x * blockDim.x + threadIdx.x;
    if (e < N_EDGES) atomicAdd(&g_cnt[edge_at(ei, N_EDGES + e)], 1);
}

// ---- two-phase scan: 8 blocks x 1024 threads each ----
__global__ __launch_bounds__(1024) void k_scan1() {
    const int b = blockIdx.x, t = threadIdx.x;
    const int i = b * 1024 + t;
    const int lane = t & 31, warp = t >> 5;
    int v = g_cnt[i];
    int inc = v;
    #pragma unroll
    for (int o = 1; o < 32; o <<= 1) {
        int y = __shfl_up_sync(0xffffffffu, inc, o);
        if (lane >= o) inc += y;
    }
    __shared__ int wsum[32];
    __shared__ int btot;
    if (lane == 31) wsum[warp] = inc;
    __syncthreads();
    if (warp == 0) {
        int ws = wsum[lane];
        int wi = ws;
        #pragma unroll
        for (int o = 1; o < 32; o <<= 1) {
            int y = __shfl_up_sync(0xffffffffu, wi, o);
            if (lane >= o) wi += y;
        }
        wsum[lane] = wi - ws;
        if (lane == 31) btot = wi;
    }
    __syncthreads();
    g_off[i] = wsum[warp] + inc - v;    // block-local exclusive prefix
    g_dinv[i] = rsqrtf((float)(v + 1));
    if (t == 0) g_bsum[b] = btot;
}
__global__ __launch_bounds__(1024) void k_scan2() {
    const int b = blockIdx.x, t = threadIdx.x;
    const int i = b * 1024 + t;
    int base = 0, tot = 0;
    #pragma unroll
    for (int j = 0; j < 8; j++) {
        int s = g_bsum[j];
        if (j < b) base += s;
        tot += s;
    }
    int o = g_off[i] + base;
    g_off[i] = o;
    g_cursor[i] = o;
    if (b == 7 && t == 1023) g_off[N_NODES] = tot;
}

__global__ void k_fill(const void* __restrict__ ei) {
    int e = blockIdx.x * blockDim.x + threadIdx.x;
    if (e >= N_EDGES) return;
    int s = edge_at(ei, e);
    int d = edge_at(ei, N_EDGES + e);
    int pos = atomicAdd(&g_cursor[d], 1);
    g_csr_src[pos] = s;
}

// ---- gather aggregation (warp per node) + fp16 write ----
__global__ __launch_bounds__(256) void k_gather(const float* __restrict__ x) {
    int v = blockIdx.x * 8 + (threadIdx.x >> 5);
    int lane = threadIdx.x & 31;
    float dv = g_dinv[v];
    const float4* xv = reinterpret_cast<const float4*>(x + (size_t)v * IN_DIM);
    float4 acc[6];
    float sw = dv * dv;
    #pragma unroll
    for (int t = 0; t < 6; t++) {
        float4 a = xv[lane + 32 * t];
        acc[t].x = a.x * sw; acc[t].y = a.y * sw;
        acc[t].z = a.z * sw; acc[t].w = a.w * sw;
    }
    int e0 = g_off[v], e1 = g_off[v + 1];
    for (int p = e0; p < e1; p++) {
        int s = g_csr_src[p];
        float w = g_dinv[s] * dv;
        const float4* xs = reinterpret_cast<const float4*>(x + (size_t)s * IN_DIM);
        #pragma unroll
        for (int t = 0; t < 6; t++) {
            float4 a = xs[lane + 32 * t];
            acc[t].x += a.x * w; acc[t].y += a.y * w;
            acc[t].z += a.z * w; acc[t].w += a.w * w;
        }
    }
    #pragma unroll
    for (int t = 0; t < 6; t++) {
        int eb = v * IN_DIM + lane * 4 + 128 * t;
        __half2 h01 = __halves2half2(__float2half(acc[t].x), __float2half(acc[t].y));
        __half2 h23 = __halves2half2(__float2half(acc[t].z), __float2half(acc[t].w));
        *reinterpret_cast<uint2*>(g_a_hi + eb) =
            make_uint2(*(uint32_t*)&h01, *(uint32_t*)&h23);
    }
}

// ============================ HMMA GEMM (single-term fp16, KC=64) ============================
// Per 64-wide k-chunk, stage {Ah, Bh} (32KB); 3-stage cp.async pipeline (96KB).
// Block tile 128x128, 8 warps (2M x 4N), warp tile 64x32. Rows are 128B (8x16B chunks).
#define KCHUNK 12
#define STAGE_B 32768
#define H_STRIDE 130
#define W2S_OFF 98304
#define B1S_OFF (W2S_OFF + 8192)
#define SMEM_TOTAL (B1S_OFF + 512)

__global__ __launch_bounds__(256, 2) void k_gemm_mma(const float* __restrict__ b1,
                                                     const float* __restrict__ W2) {
    extern __shared__ __align__(128) char smem[];
    const uint32_t sb = smem_to_u32(smem);
    const int tid = threadIdx.x, lane = tid & 31, wid = tid >> 5;
    const int wm = wid & 1, wn = wid >> 1;
    const int bx = blockIdx.x, by = blockIdx.y;

    // stage W2 slice (128x16 f32) + b1 slice (128 f32)
    {
        const float4* s = reinterpret_cast<const float4*>(W2 + (size_t)bx * 128 * N_CLASSES);
        float4* d = reinterpret_cast<float4*>(smem + W2S_OFF);
        #pragma unroll
        for (int i = tid; i < 512; i += 256) d[i] = s[i];
        if (tid < 128) reinterpret_cast<float*>(smem + B1S_OFF)[tid] = b1[bx * 128 + tid];
    }

    float c[4][4][4];
    #pragma unroll
    for (int mi = 0; mi < 4; mi++)
        #pragma unroll
        for (int ni = 0; ni < 4; ni++)
            #pragma unroll
            for (int q = 0; q < 4; q++) c[mi][ni][q] = 0.0f;

    const int arow_g = by * 128;
    const int brow_g = bx * 128;

    // per-stage: A = 128 rows x 128 B (1024 16B-lines), B same; 4 lines each per thread
    auto load_stage = [&](int ch, int buf) {
        int kk = ch * 64;
        uint32_t sbase = sb + buf * STAGE_B;
        #pragma unroll
        for (int i = 0; i < 4; i++) {
            int l = tid + i * 256;
            int row = l >> 3;            // 0..127
            int chk = l & 7;             // 0..7
            uint32_t soff = row * 128 + ((chk ^ (row & 7)) << 4);
            size_t goff = (size_t)row * IN_DIM + kk + chk * 8;
            CP_ASYNC16(sbase +     0 + soff, g_a_hi  + (size_t)arow_g * IN_DIM + goff);
            CP_ASYNC16(sbase + 16384 + soff, g_bt_hi + (size_t)brow_g * IN_DIM + goff);
        }
        CP_COMMIT();
    };

    load_stage(0, 0);
    load_stage(1, 1);

    #pragma unroll 3
    for (int ch = 0; ch < KCHUNK; ch++) {
        if (ch + 2 < KCHUNK) { CP_WAIT(1); } else { CP_WAIT(0); }
        __syncthreads();
        if (ch + 2 < KCHUNK) load_stage(ch + 2, (ch + 2) % 3);

        uint32_t aHB = sb + (ch % 3) * STAGE_B;
        uint32_t bHB = aHB + 16384;

        #pragma unroll
        for (int kk = 0; kk < 4; kk++) {
            uint32_t a[4][4], bh[4][2];
            int arow = wm * 64 + (lane & 15);
            int akc = kk * 2 + (lane >> 4);      // 0..7
            #pragma unroll
            for (int mi = 0; mi < 4; mi++) {
                int row = arow + mi * 16;
                ldsm4(a[mi], aHB + row * 128 + ((akc ^ (row & 7)) << 4));
            }
            int bnl = (lane & 7) + ((lane >> 4) << 3);
            int bkc = kk * 2 + ((lane >> 3) & 1);
            #pragma unroll
            for (int nn = 0; nn < 2; nn++) {
                int n = wn * 32 + nn * 16 + bnl;
                uint32_t t[4];
                ldsm4(t, bHB + n * 128 + ((bkc ^ (n & 7)) << 4));
                bh[nn * 2][0] = t[0]; bh[nn * 2][1] = t[1];
                bh[nn * 2 + 1][0] = t[2]; bh[nn * 2 + 1][1] = t[3];
            }
            #pragma unroll
            for (int mi = 0; mi < 4; mi++)
                #pragma unroll
                for (int ni = 0; ni < 4; ni++)
                    mma16816(c[mi][ni], a[mi], bh[ni]);
        }
    }

    // epilogue: stage h to smem, then h @ W2 slice -> atomic logits
    __syncthreads();
    float* h = reinterpret_cast<float*>(smem);
    const float* b1s = reinterpret_cast<const float*>(smem + B1S_OFF);
    #pragma unroll
    for (int mi = 0; mi < 4; mi++) {
        int r0 = wm * 64 + mi * 16 + (lane >> 2);
        #pragma unroll
        for (int ni = 0; ni < 4; ni++) {
            int n = wn * 32 + ni * 8 + (lane & 3) * 2;
            *reinterpret_cast<float2*>(&h[r0 * H_STRIDE + n]) =
                make_float2(c[mi][ni][0], c[mi][ni][1]);
            *reinterpret_cast<float2*>(&h[(r0 + 8) * H_STRIDE + n]) =
                make_float2(c[mi][ni][2], c[mi][ni][3]);
        }
    }
    __syncthreads();
    {
        int r = tid >> 1;
        int cg = (tid & 1) * 8;
        const float* w2s = reinterpret_cast<const float*>(smem + W2S_OFF);
        float acc[8];
        #pragma unroll
        for (int q = 0; q < 8; q++) acc[q] = 0.0f;
        #pragma unroll 4
        for (int n = 0; n < 128; n++) {
            float hv = fmaxf(h[r * H_STRIDE + n] + b1s[n], 0.0f);
            const float4* w = reinterpret_cast<const float4*>(w2s + n * N_CLASSES + cg);
            float4 w0 = w[0], w1 = w[1];
            acc[0] += hv * w0.x; acc[1] += hv * w0.y;
            acc[2] += hv * w0.z; acc[3] += hv * w0.w;
            acc[4] += hv * w1.x; acc[5] += hv * w1.y;
            acc[6] += hv * w1.z; acc[7] += hv * w1.w;
        }
        float* lg = &g_logits[(by * 128 + r) * N_CLASSES + cg];
        #pragma unroll
        for (int q = 0; q < 8; q++) atomicAdd(&lg[q], acc[q]);
    }
}

// ---- log_softmax over 16 classes ----
__global__ void k_lsm(const float* __restrict__ b2, float* __restrict__ out) {
    int t = blockIdx.x * blockDim.x + threadIdx.x;
    if (t >= N_NODES * N_CLASSES) return;
    int c = t & 15;
    float v = g_logits[t] + b2[c];
    float m = v;
    #pragma unroll
    for (int k = 8; k > 0; k >>= 1)
        m = fmaxf(m, __shfl_xor_sync(0xffffffffu, m, k, 16));
    float s = __expf(v - m);
    #pragma unroll
    for (int k = 8; k > 0; k >>= 1)
        s += __shfl_xor_sync(0xffffffffu, s, k, 16);
    out[t] = v - m - __logf(s);
}

// ---- eager module load ----
namespace {
struct EagerLoad {
    EagerLoad() {
        void* p = nullptr;
        cudaGetSymbolAddress(&p, g_logits);
        cudaGetSymbolAddress(&p, g_dinv);
        cudaGetSymbolAddress(&p, g_is64);
        cudaGetSymbolAddress(&p, g_cnt);
        cudaGetSymbolAddress(&p, g_off);
        cudaGetSymbolAddress(&p, g_cursor);
        cudaGetSymbolAddress(&p, g_csr_src);
        cudaGetSymbolAddress(&p, g_bsum);
        cudaGetSymbolAddress(&p, g_a_hi);
        cudaGetSymbolAddress(&p, g_bt_hi);
        cudaFuncAttributes a;
        cudaFuncGetAttributes(&a, k_prep_all);
        cudaFuncGetAttributes(&a, k_hist);
        cudaFuncGetAttributes(&a, k_scan1);
        cudaFuncGetAttributes(&a, k_scan2);
        cudaFuncGetAttributes(&a, k_fill);
        cudaFuncGetAttributes(&a, k_gather);
        cudaFuncGetAttributes(&a, k_gemm_mma);
        cudaFuncGetAttributes(&a, k_lsm);
        cudaFuncSetAttribute(k_gemm_mma, cudaFuncAttributeMaxDynamicSharedMemorySize, SMEM_TOTAL);
    }
};
EagerLoad g_eager_load;
}

extern "C" void kernel_launch(void* const* d_in, const int* in_sizes, int n_in,
                              void* d_out, int out_size) {
    const float* x  = (const float*)d_in[0];
    const void*  ei = d_in[1];                 // [2, E], int32 OR int64 (detected)
    const float* W1 = (const float*)d_in[2];
    const float* b1 = (const float*)d_in[3];
    const float* W2 = (const float*)d_in[4];
    const float* b2 = (const float*)d_in[5];
    float* out = (float*)d_out;

    k_prep_all<<<3201, 256>>>(W1, (const int*)ei);
    k_hist<<<(N_EDGES + 255) / 256, 256>>>(ei);
    k_scan1<<<8, 1024>>>();
    k_scan2<<<8, 1024>>>();
    k_fill<<<(N_EDGES + 255) / 256, 256>>>(ei);
    k_gather<<<N_NODES / 8, 256>>>(x);

    k_gemm_mma<<<dim3(HIDDEN / 128, N_NODES / 128), 256, SMEM_TOTAL>>>(b1, W2);
    k_lsm<<<(N_NODES * N_CLASSES + 255) / 256, 256>>>(b2, out);
}